// round 2
// baseline (speedup 1.0000x reference)
#include <cuda_runtime.h>
#include <math.h>

// Problem dims
#define S_   1024
#define H_   4096
#define NH_  32
#define HD_  128
#define F_   11008
#define OUT_ 512

// ---------------------------------------------------------------------------
// Scratch (device globals; no allocation allowed)
// ---------------------------------------------------------------------------
__device__ float g_h  [S_ * H_];   // residual stream
__device__ float g_a  [S_ * H_];   // normed activations
__device__ float g_q  [S_ * H_];
__device__ float g_k  [S_ * H_];
__device__ float g_v  [S_ * H_];
__device__ float g_att[S_ * H_];
__device__ float g_g1 [S_ * F_];   // gate proj (then swiglu product)
__device__ float g_g2 [S_ * F_];   // up proj

// ---------------------------------------------------------------------------
// Embedding gather: h[s, :] = embed[x[s], :]
// ---------------------------------------------------------------------------
__global__ void embed_kernel(const int* __restrict__ x,
                             const float* __restrict__ E,
                             float* __restrict__ out) {
    int idx = blockIdx.x * blockDim.x + threadIdx.x;   // over S_*H_
    int s = idx >> 12;           // /4096
    int c = idx & (H_ - 1);
    out[idx] = E[(long long)x[s] * H_ + c];
}

// ---------------------------------------------------------------------------
// RMSNorm: out = x * rsqrt(mean(x^2)+eps) * w     (one block per row)
// ---------------------------------------------------------------------------
__global__ void __launch_bounds__(256) rmsnorm_kernel(const float* __restrict__ x,
                                                      const float* __restrict__ w,
                                                      float* __restrict__ out) {
    int row = blockIdx.x;
    const float4* xr = (const float4*)(x + row * H_);
    float s = 0.f;
    for (int i = threadIdx.x; i < H_ / 4; i += 256) {
        float4 v = xr[i];
        s += v.x * v.x + v.y * v.y + v.z * v.z + v.w * v.w;
    }
    __shared__ float red[256];
    red[threadIdx.x] = s;
    __syncthreads();
    for (int o = 128; o; o >>= 1) {
        if (threadIdx.x < o) red[threadIdx.x] += red[threadIdx.x + o];
        __syncthreads();
    }
    float scale = rsqrtf(red[0] * (1.0f / H_) + 1e-6f);
    const float4* wr = (const float4*)w;
    float4* orow = (float4*)(out + row * H_);
    for (int i = threadIdx.x; i < H_ / 4; i += 256) {
        float4 v = xr[i], g = wr[i];
        orow[i] = make_float4(v.x * scale * g.x, v.y * scale * g.y,
                              v.z * scale * g.z, v.w * scale * g.w);
    }
}

// ---------------------------------------------------------------------------
// RoPE (in-place on q and k, layout [S, NH, HD])
// ---------------------------------------------------------------------------
__global__ void rope_kernel(float* __restrict__ q, float* __restrict__ k) {
    int idx = blockIdx.x * blockDim.x + threadIdx.x;   // over S_*NH_*64
    int i = idx & 63;
    int t = idx >> 6;
    int h = t & (NH_ - 1);
    int s = t >> 5;
    float inv = (float)exp(-(double)i / 64.0 * 9.210340371976184); // ln(10000)
    float ang = (float)s * inv;
    float sn, c;
    sincosf(ang, &sn, &c);
    int base = s * H_ + h * HD_ + i;
    float q1 = q[base], q2 = q[base + 64];
    q[base]      = q1 * c - q2 * sn;
    q[base + 64] = q2 * c + q1 * sn;
    float k1 = k[base], k2 = k[base + 64];
    k[base]      = k1 * c - k2 * sn;
    k[base + 64] = k2 * c + k1 * sn;
}

// ---------------------------------------------------------------------------
// Flash-style causal attention.
// grid (NH, S/32); block 256 = 8 warps; each warp owns 4 queries.
// Lane c of a warp holds dims [lane*4, lane*4+4) of q/acc.
// ---------------------------------------------------------------------------
#define TK 32
__global__ void __launch_bounds__(256) attn_kernel(const float* __restrict__ Q,
                                                   const float* __restrict__ K,
                                                   const float* __restrict__ V,
                                                   float* __restrict__ O) {
    int h = blockIdx.x;
    int q0 = blockIdx.y * 32;
    int tid = threadIdx.x, warp = tid >> 5, lane = tid & 31;
    __shared__ float Ks[TK * HD_];
    __shared__ float Vs[TK * HD_];

    const float scale = 0.08838834764831845f;  // 1/sqrt(128)
    float qreg[4][4], m[4], l[4], acc[4][4];
#pragma unroll
    for (int j = 0; j < 4; j++) {
        int sj = q0 + warp * 4 + j;
        float4 qv = *(const float4*)(Q + sj * H_ + h * HD_ + lane * 4);
        qreg[j][0] = qv.x; qreg[j][1] = qv.y; qreg[j][2] = qv.z; qreg[j][3] = qv.w;
        m[j] = -1e30f; l[j] = 0.f;
        acc[j][0] = acc[j][1] = acc[j][2] = acc[j][3] = 0.f;
    }
    int loadRow = tid >> 3;            // 32 rows, 8 threads/row
    int loadCol = (tid & 7) * 16;      // 16 floats per thread per row

    for (int t0 = 0; t0 <= q0 + 31; t0 += TK) {
#pragma unroll
        for (int r = 0; r < 4; r++) {
            int col = loadCol + r * 4;
            *(float4*)(Ks + loadRow * HD_ + col) =
                *(const float4*)(K + (t0 + loadRow) * H_ + h * HD_ + col);
            *(float4*)(Vs + loadRow * HD_ + col) =
                *(const float4*)(V + (t0 + loadRow) * H_ + h * HD_ + col);
        }
        __syncthreads();
#pragma unroll 4
        for (int t = 0; t < TK; t++) {
            float4 kv = *(const float4*)(Ks + t * HD_ + lane * 4);
            float p[4];
#pragma unroll
            for (int j = 0; j < 4; j++)
                p[j] = qreg[j][0] * kv.x + qreg[j][1] * kv.y +
                       qreg[j][2] * kv.z + qreg[j][3] * kv.w;
#pragma unroll
            for (int off = 16; off; off >>= 1) {
#pragma unroll
                for (int j = 0; j < 4; j++)
                    p[j] += __shfl_xor_sync(0xffffffffu, p[j], off);
            }
            float4 vv = *(const float4*)(Vs + t * HD_ + lane * 4);
            int tg = t0 + t;
#pragma unroll
            for (int j = 0; j < 4; j++) {
                int sj = q0 + warp * 4 + j;
                float sc = (tg <= sj) ? p[j] * scale : -1e30f;
                float mn = fmaxf(m[j], sc);
                float corr = __expf(m[j] - mn);
                float w = __expf(sc - mn);
                l[j] = l[j] * corr + w;
                m[j] = mn;
                acc[j][0] = acc[j][0] * corr + w * vv.x;
                acc[j][1] = acc[j][1] * corr + w * vv.y;
                acc[j][2] = acc[j][2] * corr + w * vv.z;
                acc[j][3] = acc[j][3] * corr + w * vv.w;
            }
        }
        __syncthreads();
    }
#pragma unroll
    for (int j = 0; j < 4; j++) {
        int sj = q0 + warp * 4 + j;
        float inv = 1.f / l[j];
        *(float4*)(O + sj * H_ + h * HD_ + lane * 4) =
            make_float4(acc[j][0] * inv, acc[j][1] * inv,
                        acc[j][2] * inv, acc[j][3] * inv);
    }
}

// ---------------------------------------------------------------------------
// SwiGLU: g = silu(g) * u
// ---------------------------------------------------------------------------
__global__ void swiglu_kernel(float* __restrict__ g, const float* __restrict__ u, int n) {
    int i = blockIdx.x * blockDim.x + threadIdx.x;
    if (i < n) {
        float x = g[i];
        float sig = 1.f / (1.f + expf(-x));
        g[i] = x * sig * u[i];
    }
}

// ---------------------------------------------------------------------------
// SGEMM: C (MxN) = A (MxK, row-major) @ B (KxN, row-major)
// MODE 0: C = AB ; MODE 1: C += AB ; MODE 2: C = AB + bias[col]
// BM=BN=128, BK=16, TM=TN=8, 256 threads.
// Double-buffered smem with register staging: ONE __syncthreads per k-slab,
// global prefetch issued before the FFMA block to hide DRAM/L2 latency.
// All problem dims divide the tile sizes evenly.
// ---------------------------------------------------------------------------
template <int MODE>
__global__ void __launch_bounds__(256) sgemm_kernel(const float* __restrict__ A,
                                                    const float* __restrict__ B,
                                                    float* __restrict__ C,
                                                    const float* __restrict__ bias,
                                                    int M, int N, int K) {
    const int BM = 128, BN = 128, BK = 16, TM = 8, TN = 8;
    int cRow = blockIdx.y, cCol = blockIdx.x;
    const float* Ab = A + (long long)cRow * BM * K;
    const float* Bb = B + cCol * BN;
    C += (long long)cRow * BM * N + cCol * BN;

    __shared__ float As[2][BK][BM];   // transposed: As[k][m]
    __shared__ float Bs[2][BK][BN];

    int tid = threadIdx.x;
    // A tile loads: 128 rows x 16 cols = 2048 floats -> 2 float4/thread
    int aRow = tid >> 2;              // 0..63
    int aCol = (tid & 3) * 4;         // 0,4,8,12
    // B tile loads: 16 rows x 128 cols = 2048 floats -> 2 float4/thread
    int bRow = tid >> 5;              // 0..7
    int bCol = (tid & 31) * 4;        // 0..124
    int threadRow = tid >> 4;         // 0..15
    int threadCol = tid & 15;         // 0..15

    float acc[TM][TN];
#pragma unroll
    for (int i = 0; i < TM; i++)
#pragma unroll
        for (int j = 0; j < TN; j++) acc[i][j] = 0.f;

    // Prologue: load slab 0 into buffer 0
    {
#pragma unroll
        for (int r = 0; r < 2; r++) {
            int row = aRow + r * 64;
            float4 v = *(const float4*)(Ab + (long long)row * K + aCol);
            As[0][aCol + 0][row] = v.x;
            As[0][aCol + 1][row] = v.y;
            As[0][aCol + 2][row] = v.z;
            As[0][aCol + 3][row] = v.w;
        }
#pragma unroll
        for (int r = 0; r < 2; r++) {
            int row = bRow + r * 8;
            *(float4*)(&Bs[0][row][bCol]) =
                *(const float4*)(Bb + (long long)row * N + bCol);
        }
    }
    __syncthreads();

    int buf = 0;
    for (int k0 = 0; k0 < K; k0 += BK) {
        // Prefetch next slab into registers (before compute, to overlap)
        float4 aReg[2], bReg[2];
        bool has_next = (k0 + BK < K);
        if (has_next) {
            const float* Ag = Ab + (k0 + BK);
            const float* Bg = Bb + (long long)(k0 + BK) * N;
#pragma unroll
            for (int r = 0; r < 2; r++)
                aReg[r] = *(const float4*)(Ag + (long long)(aRow + r * 64) * K + aCol);
#pragma unroll
            for (int r = 0; r < 2; r++)
                bReg[r] = *(const float4*)(Bg + (long long)(bRow + r * 8) * N + bCol);
        }

        // Compute current slab
#pragma unroll
        for (int k = 0; k < BK; k++) {
            float regM[TM], regN[TN];
#pragma unroll
            for (int i = 0; i < TM; i++) regM[i] = As[buf][k][threadRow * TM + i];
#pragma unroll
            for (int j = 0; j < TN; j++) regN[j] = Bs[buf][k][threadCol * TN + j];
#pragma unroll
            for (int i = 0; i < TM; i++)
#pragma unroll
                for (int j = 0; j < TN; j++)
                    acc[i][j] += regM[i] * regN[j];
        }

        if (has_next) {
            int nb = buf ^ 1;
#pragma unroll
            for (int r = 0; r < 2; r++) {
                int row = aRow + r * 64;
                As[nb][aCol + 0][row] = aReg[r].x;
                As[nb][aCol + 1][row] = aReg[r].y;
                As[nb][aCol + 2][row] = aReg[r].z;
                As[nb][aCol + 3][row] = aReg[r].w;
            }
#pragma unroll
            for (int r = 0; r < 2; r++) {
                int row = bRow + r * 8;
                *(float4*)(&Bs[nb][row][bCol]) = bReg[r];
            }
            __syncthreads();
            buf = nb;
        }
    }

#pragma unroll
    for (int i = 0; i < TM; i++) {
        int row = threadRow * TM + i;
#pragma unroll
        for (int j4 = 0; j4 < TN; j4 += 4) {
            int col = threadCol * TN + j4;
            float4 r = make_float4(acc[i][j4 + 0], acc[i][j4 + 1],
                                   acc[i][j4 + 2], acc[i][j4 + 3]);
            if (MODE == 1) {
                float4 old = *(float4*)(C + (long long)row * N + col);
                r.x += old.x; r.y += old.y; r.z += old.z; r.w += old.w;
            } else if (MODE == 2) {
                float4 b = *(const float4*)(bias + cCol * BN + col);
                r.x += b.x; r.y += b.y; r.z += b.z; r.w += b.w;
            }
            *(float4*)(C + (long long)row * N + col) = r;
        }
    }
}

// ---------------------------------------------------------------------------
// Host driver (graph-capturable: kernel launches only)
// ---------------------------------------------------------------------------
static inline float* sym(const void* s) {
    void* p = nullptr;
    cudaGetSymbolAddress(&p, s);
    return (float*)p;
}

extern "C" void kernel_launch(void* const* d_in, const int* in_sizes, int n_in,
                              void* d_out, int out_size) {
    const int*   x     = (const int*)  d_in[0];
    const float* embed = (const float*)d_in[1];
    const float* Wq    = (const float*)d_in[2];
    const float* Wk    = (const float*)d_in[3];
    const float* Wv    = (const float*)d_in[4];
    const float* Wo    = (const float*)d_in[5];
    const float* Wg    = (const float*)d_in[6];
    const float* Wu    = (const float*)d_in[7];
    const float* Wd    = (const float*)d_in[8];
    const float* ln1   = (const float*)d_in[9];
    const float* ln2   = (const float*)d_in[10];
    const float* lnf   = (const float*)d_in[11];
    const float* Wout  = (const float*)d_in[12];
    const float* bout  = (const float*)d_in[13];
    float* out = (float*)d_out;

    float* h   = sym(g_h);
    float* a   = sym(g_a);
    float* q   = sym(g_q);
    float* k   = sym(g_k);
    float* v   = sym(g_v);
    float* att = sym(g_att);
    float* gg  = sym(g_g1);
    float* uu  = sym(g_g2);

    dim3 gHH(H_ / 128, S_ / 128);     // N=H
    dim3 gHF(F_ / 128, S_ / 128);     // N=F
    dim3 gFH(H_ / 128, S_ / 128);     // N=H, K=F
    dim3 gOut(OUT_ / 128, S_ / 128);  // head

    embed_kernel<<<(S_ * H_) / 256, 256>>>(x, embed, h);

    for (int l = 0; l < 2; l++) {
        const float* wq = Wq + (long long)l * H_ * H_;
        const float* wk = Wk + (long long)l * H_ * H_;
        const float* wv = Wv + (long long)l * H_ * H_;
        const float* wo = Wo + (long long)l * H_ * H_;
        const float* wg = Wg + (long long)l * H_ * F_;
        const float* wu = Wu + (long long)l * H_ * F_;
        const float* wd = Wd + (long long)l * F_ * H_;

        rmsnorm_kernel<<<S_, 256>>>(h, ln1 + l * H_, a);
        sgemm_kernel<0><<<gHH, 256>>>(a, wq, q, nullptr, S_, H_, H_);
        sgemm_kernel<0><<<gHH, 256>>>(a, wk, k, nullptr, S_, H_, H_);
        sgemm_kernel<0><<<gHH, 256>>>(a, wv, v, nullptr, S_, H_, H_);
        rope_kernel<<<(S_ * NH_ * 64) / 256, 256>>>(q, k);
        attn_kernel<<<dim3(NH_, S_ / 32), 256>>>(q, k, v, att);
        sgemm_kernel<1><<<gHH, 256>>>(att, wo, h, nullptr, S_, H_, H_);  // h += att @ wo

        rmsnorm_kernel<<<S_, 256>>>(h, ln2 + l * H_, a);
        sgemm_kernel<0><<<gHF, 256>>>(a, wg, gg, nullptr, S_, F_, H_);
        sgemm_kernel<0><<<gHF, 256>>>(a, wu, uu, nullptr, S_, F_, H_);
        swiglu_kernel<<<(S_ * F_) / 256, 256>>>(gg, uu, S_ * F_);
        sgemm_kernel<1><<<gFH, 256>>>(gg, wd, h, nullptr, S_, H_, F_);   // h += f @ wd
    }

    rmsnorm_kernel<<<S_, 256>>>(h, lnf, a);
    sgemm_kernel<2><<<gOut, 256>>>(a, Wout, out, bout, S_, OUT_, H_);
}

// round 6
// speedup vs baseline: 1.8162x; 1.8162x over previous
#include <cuda_runtime.h>
#include <cuda_bf16.h>
#include <math.h>

// Problem dims
#define S_   1024
#define H_   4096
#define NH_  32
#define HD_  128
#define F_   11008
#define OUT_ 512

// ---------------------------------------------------------------------------
// Scratch (device globals; no allocation allowed)
// ---------------------------------------------------------------------------
__device__ float g_h  [S_ * H_];
__device__ float g_a  [S_ * H_];
__device__ float g_q  [S_ * H_];
__device__ float g_k  [S_ * H_];
__device__ float g_v  [S_ * H_];
__device__ float g_att[S_ * H_];
__device__ float g_g1 [S_ * F_];
__device__ float g_g2 [S_ * F_];

// ---------------------------------------------------------------------------
// Embedding gather
// ---------------------------------------------------------------------------
__global__ void embed_kernel(const int* __restrict__ x,
                             const float* __restrict__ E,
                             float* __restrict__ out) {
    int idx = blockIdx.x * blockDim.x + threadIdx.x;
    int s = idx >> 12;
    int c = idx & (H_ - 1);
    out[idx] = E[(long long)x[s] * H_ + c];
}

// ---------------------------------------------------------------------------
// RMSNorm
// ---------------------------------------------------------------------------
__global__ void __launch_bounds__(256) rmsnorm_kernel(const float* __restrict__ x,
                                                      const float* __restrict__ w,
                                                      float* __restrict__ out) {
    int row = blockIdx.x;
    const float4* xr = (const float4*)(x + row * H_);
    float s = 0.f;
    for (int i = threadIdx.x; i < H_ / 4; i += 256) {
        float4 v = xr[i];
        s += v.x * v.x + v.y * v.y + v.z * v.z + v.w * v.w;
    }
    __shared__ float red[256];
    red[threadIdx.x] = s;
    __syncthreads();
    for (int o = 128; o; o >>= 1) {
        if (threadIdx.x < o) red[threadIdx.x] += red[threadIdx.x + o];
        __syncthreads();
    }
    float scale = rsqrtf(red[0] * (1.0f / H_) + 1e-6f);
    const float4* wr = (const float4*)w;
    float4* orow = (float4*)(out + row * H_);
    for (int i = threadIdx.x; i < H_ / 4; i += 256) {
        float4 v = xr[i], g = wr[i];
        orow[i] = make_float4(v.x * scale * g.x, v.y * scale * g.y,
                              v.z * scale * g.z, v.w * scale * g.w);
    }
}

// ---------------------------------------------------------------------------
// RoPE (in-place on q and k, layout [S, NH, HD])
// ---------------------------------------------------------------------------
__global__ void rope_kernel(float* __restrict__ q, float* __restrict__ k) {
    int idx = blockIdx.x * blockDim.x + threadIdx.x;
    int i = idx & 63;
    int t = idx >> 6;
    int h = t & (NH_ - 1);
    int s = t >> 5;
    float inv = (float)exp(-(double)i / 64.0 * 9.210340371976184);
    float ang = (float)s * inv;
    float sn, c;
    sincosf(ang, &sn, &c);
    int base = s * H_ + h * HD_ + i;
    float q1 = q[base], q2 = q[base + 64];
    q[base]      = q1 * c - q2 * sn;
    q[base + 64] = q2 * c + q1 * sn;
    float k1 = k[base], k2 = k[base + 64];
    k[base]      = k1 * c - k2 * sn;
    k[base + 64] = k2 * c + k1 * sn;
}

// ---------------------------------------------------------------------------
// Flash-style causal attention
// ---------------------------------------------------------------------------
#define TK 32
__global__ void __launch_bounds__(256) attn_kernel(const float* __restrict__ Q,
                                                   const float* __restrict__ K,
                                                   const float* __restrict__ V,
                                                   float* __restrict__ O) {
    int h = blockIdx.x;
    int q0 = blockIdx.y * 32;
    int tid = threadIdx.x, warp = tid >> 5, lane = tid & 31;
    __shared__ float Ks[TK * HD_];
    __shared__ float Vs[TK * HD_];

    const float scale = 0.08838834764831845f;
    float qreg[4][4], m[4], l[4], acc[4][4];
#pragma unroll
    for (int j = 0; j < 4; j++) {
        int sj = q0 + warp * 4 + j;
        float4 qv = *(const float4*)(Q + sj * H_ + h * HD_ + lane * 4);
        qreg[j][0] = qv.x; qreg[j][1] = qv.y; qreg[j][2] = qv.z; qreg[j][3] = qv.w;
        m[j] = -1e30f; l[j] = 0.f;
        acc[j][0] = acc[j][1] = acc[j][2] = acc[j][3] = 0.f;
    }
    int loadRow = tid >> 3;
    int loadCol = (tid & 7) * 16;

    for (int t0 = 0; t0 <= q0 + 31; t0 += TK) {
#pragma unroll
        for (int r = 0; r < 4; r++) {
            int col = loadCol + r * 4;
            *(float4*)(Ks + loadRow * HD_ + col) =
                *(const float4*)(K + (t0 + loadRow) * H_ + h * HD_ + col);
            *(float4*)(Vs + loadRow * HD_ + col) =
                *(const float4*)(V + (t0 + loadRow) * H_ + h * HD_ + col);
        }
        __syncthreads();
#pragma unroll 4
        for (int t = 0; t < TK; t++) {
            float4 kv = *(const float4*)(Ks + t * HD_ + lane * 4);
            float p[4];
#pragma unroll
            for (int j = 0; j < 4; j++)
                p[j] = qreg[j][0] * kv.x + qreg[j][1] * kv.y +
                       qreg[j][2] * kv.z + qreg[j][3] * kv.w;
#pragma unroll
            for (int off = 16; off; off >>= 1) {
#pragma unroll
                for (int j = 0; j < 4; j++)
                    p[j] += __shfl_xor_sync(0xffffffffu, p[j], off);
            }
            float4 vv = *(const float4*)(Vs + t * HD_ + lane * 4);
            int tg = t0 + t;
#pragma unroll
            for (int j = 0; j < 4; j++) {
                int sj = q0 + warp * 4 + j;
                float sc = (tg <= sj) ? p[j] * scale : -1e30f;
                float mn = fmaxf(m[j], sc);
                float corr = __expf(m[j] - mn);
                float w = __expf(sc - mn);
                l[j] = l[j] * corr + w;
                m[j] = mn;
                acc[j][0] = acc[j][0] * corr + w * vv.x;
                acc[j][1] = acc[j][1] * corr + w * vv.y;
                acc[j][2] = acc[j][2] * corr + w * vv.z;
                acc[j][3] = acc[j][3] * corr + w * vv.w;
            }
        }
        __syncthreads();
    }
#pragma unroll
    for (int j = 0; j < 4; j++) {
        int sj = q0 + warp * 4 + j;
        float inv = 1.f / l[j];
        *(float4*)(O + sj * H_ + h * HD_ + lane * 4) =
            make_float4(acc[j][0] * inv, acc[j][1] * inv,
                        acc[j][2] * inv, acc[j][3] * inv);
    }
}

// ---------------------------------------------------------------------------
// SwiGLU
// ---------------------------------------------------------------------------
__global__ void swiglu_kernel(float* __restrict__ g, const float* __restrict__ u, int n) {
    int i = blockIdx.x * blockDim.x + threadIdx.x;
    if (i < n) {
        float x = g[i];
        float sig = 1.f / (1.f + expf(-x));
        g[i] = x * sig * u[i];
    }
}

// ---------------------------------------------------------------------------
// Tensor-core GEMM with bf16 hi/lo split (fp32-grade accuracy):
//   C = Ahi*Bhi + Ahi*Blo + Alo*Bhi   (fp32 accumulate)
// mma.sync.m16n8k16.bf16 + ldmatrix.  BM=BN=128, BK=16, 256 thr (8 warps),
// warp tile 64x32, reg-staged double-buffered smem (1 sync/slab).
// MODE 0: C = AB ; MODE 1: C += AB ; MODE 2: C = AB + bias[col]
// ---------------------------------------------------------------------------
#define AP 24    // A smem row stride (shorts): 48B -> ldmatrix conflict-free
#define BP 136   // B smem row stride (shorts): 272B -> conflict-free

__device__ __forceinline__ void ldsm4(unsigned& r0, unsigned& r1,
                                      unsigned& r2, unsigned& r3,
                                      const void* p) {
    unsigned addr = (unsigned)__cvta_generic_to_shared(p);
    asm volatile("ldmatrix.sync.aligned.m8n8.x4.shared.b16 {%0,%1,%2,%3}, [%4];"
                 : "=r"(r0), "=r"(r1), "=r"(r2), "=r"(r3) : "r"(addr));
}
__device__ __forceinline__ void ldsm4t(unsigned& r0, unsigned& r1,
                                       unsigned& r2, unsigned& r3,
                                       const void* p) {
    unsigned addr = (unsigned)__cvta_generic_to_shared(p);
    asm volatile("ldmatrix.sync.aligned.m8n8.x4.trans.shared.b16 {%0,%1,%2,%3}, [%4];"
                 : "=r"(r0), "=r"(r1), "=r"(r2), "=r"(r3) : "r"(addr));
}
__device__ __forceinline__ void mma16816(float* c, const unsigned* a, const unsigned* b) {
    asm volatile(
        "mma.sync.aligned.m16n8k16.row.col.f32.bf16.bf16.f32 "
        "{%0,%1,%2,%3}, {%4,%5,%6,%7}, {%8,%9}, {%0,%1,%2,%3};"
        : "+f"(c[0]), "+f"(c[1]), "+f"(c[2]), "+f"(c[3])
        : "r"(a[0]), "r"(a[1]), "r"(a[2]), "r"(a[3]), "r"(b[0]), "r"(b[1]));
}
// float4 -> 4 bf16 hi (packed uint2) + 4 bf16 lo
__device__ __forceinline__ void split_bf16(float4 v, uint2& hi, uint2& lo) {
    __nv_bfloat162 h0 = __floats2bfloat162_rn(v.x, v.y);
    __nv_bfloat162 h1 = __floats2bfloat162_rn(v.z, v.w);
    float2 f0 = __bfloat1622float2(h0);
    float2 f1 = __bfloat1622float2(h1);
    __nv_bfloat162 l0 = __floats2bfloat162_rn(v.x - f0.x, v.y - f0.y);
    __nv_bfloat162 l1 = __floats2bfloat162_rn(v.z - f1.x, v.w - f1.y);
    hi.x = *(unsigned*)&h0; hi.y = *(unsigned*)&h1;
    lo.x = *(unsigned*)&l0; lo.y = *(unsigned*)&l1;
}

template <int MODE>
__global__ void __launch_bounds__(256, 1) bgemm_kernel(const float* __restrict__ A,
                                                       const float* __restrict__ B,
                                                       float* __restrict__ C,
                                                       const float* __restrict__ bias,
                                                       int M, int N, int K) {
    const int BM = 128, BN = 128, BK = 16;
    int cRow = blockIdx.y, cCol = blockIdx.x;
    const float* Ab = A + (long long)cRow * BM * K;
    const float* Bb = B + cCol * BN;
    C += (long long)cRow * BM * N + cCol * BN;

    __shared__ unsigned short sAhi[2][BM][AP];
    __shared__ unsigned short sAlo[2][BM][AP];
    __shared__ unsigned short sBhi[2][BK][BP];
    __shared__ unsigned short sBlo[2][BK][BP];

    int tid = threadIdx.x;
    int lane = tid & 31;
    int warp = tid >> 5;
    int warp_m = (warp >> 2) * 64;   // 0 or 64
    int warp_n = (warp & 3) * 32;    // 0,32,64,96

    // global-load assignments
    int aRow = tid >> 1;             // 0..127
    int aCol = (tid & 1) * 8;        // 0 or 8
    int bK   = tid >> 4;             // 0..15
    int bN   = (tid & 15) * 8;       // 0..120

    float acc[4][4][4];
#pragma unroll
    for (int i = 0; i < 4; i++)
#pragma unroll
        for (int j = 0; j < 4; j++)
#pragma unroll
            for (int r = 0; r < 4; r++) acc[i][j][r] = 0.f;

    int a_r = lane & 15;
    int a_c = (lane >> 4) * 8;
    int b_r = lane & 15;

    // ---- prologue: load slab 0 -> buf 0
    {
        float4 av0 = *(const float4*)(Ab + (long long)aRow * K + aCol);
        float4 av1 = *(const float4*)(Ab + (long long)aRow * K + aCol + 4);
        float4 bv0 = *(const float4*)(Bb + (long long)bK * N + bN);
        float4 bv1 = *(const float4*)(Bb + (long long)bK * N + bN + 4);
        uint2 h, l;
        split_bf16(av0, h, l);
        *(uint2*)&sAhi[0][aRow][aCol] = h;     *(uint2*)&sAlo[0][aRow][aCol] = l;
        split_bf16(av1, h, l);
        *(uint2*)&sAhi[0][aRow][aCol + 4] = h; *(uint2*)&sAlo[0][aRow][aCol + 4] = l;
        split_bf16(bv0, h, l);
        *(uint2*)&sBhi[0][bK][bN] = h;         *(uint2*)&sBlo[0][bK][bN] = l;
        split_bf16(bv1, h, l);
        *(uint2*)&sBhi[0][bK][bN + 4] = h;     *(uint2*)&sBlo[0][bK][bN + 4] = l;
    }
    __syncthreads();

    int buf = 0;
    for (int k0 = 0; k0 < K; k0 += BK) {
        bool has_next = (k0 + BK < K);
        float4 av0, av1, bv0, bv1;
        if (has_next) {
            const float* Ag = Ab + (k0 + BK);
            const float* Bg = Bb + (long long)(k0 + BK) * N;
            av0 = *(const float4*)(Ag + (long long)aRow * K + aCol);
            av1 = *(const float4*)(Ag + (long long)aRow * K + aCol + 4);
            bv0 = *(const float4*)(Bg + (long long)bK * N + bN);
            bv1 = *(const float4*)(Bg + (long long)bK * N + bN + 4);
        }

        // ---- load fragments
        unsigned ahi[4][4], alo[4][4], bhi[4][2], blo[4][2];
#pragma unroll
        for (int mf = 0; mf < 4; mf++) {
            ldsm4(ahi[mf][0], ahi[mf][1], ahi[mf][2], ahi[mf][3],
                  &sAhi[buf][warp_m + mf * 16 + a_r][a_c]);
            ldsm4(alo[mf][0], alo[mf][1], alo[mf][2], alo[mf][3],
                  &sAlo[buf][warp_m + mf * 16 + a_r][a_c]);
        }
#pragma unroll
        for (int ng = 0; ng < 2; ng++) {
            unsigned r0, r1, r2, r3;
            int ncol = warp_n + ng * 16 + (lane >> 4) * 8;
            ldsm4t(r0, r1, r2, r3, &sBhi[buf][b_r][ncol]);
            bhi[ng * 2][0] = r0; bhi[ng * 2][1] = r1;
            bhi[ng * 2 + 1][0] = r2; bhi[ng * 2 + 1][1] = r3;
            ldsm4t(r0, r1, r2, r3, &sBlo[buf][b_r][ncol]);
            blo[ng * 2][0] = r0; blo[ng * 2][1] = r1;
            blo[ng * 2 + 1][0] = r2; blo[ng * 2 + 1][1] = r3;
        }

        // ---- 3-pass split mma
#pragma unroll
        for (int mf = 0; mf < 4; mf++)
#pragma unroll
            for (int nf = 0; nf < 4; nf++)
                mma16816(acc[mf][nf], ahi[mf], bhi[nf]);
#pragma unroll
        for (int mf = 0; mf < 4; mf++)
#pragma unroll
            for (int nf = 0; nf < 4; nf++)
                mma16816(acc[mf][nf], ahi[mf], blo[nf]);
#pragma unroll
        for (int mf = 0; mf < 4; mf++)
#pragma unroll
            for (int nf = 0; nf < 4; nf++)
                mma16816(acc[mf][nf], alo[mf], bhi[nf]);

        if (has_next) {
            int nb = buf ^ 1;
            uint2 h, l;
            split_bf16(av0, h, l);
            *(uint2*)&sAhi[nb][aRow][aCol] = h;     *(uint2*)&sAlo[nb][aRow][aCol] = l;
            split_bf16(av1, h, l);
            *(uint2*)&sAhi[nb][aRow][aCol + 4] = h; *(uint2*)&sAlo[nb][aRow][aCol + 4] = l;
            split_bf16(bv0, h, l);
            *(uint2*)&sBhi[nb][bK][bN] = h;         *(uint2*)&sBlo[nb][bK][bN] = l;
            split_bf16(bv1, h, l);
            *(uint2*)&sBhi[nb][bK][bN + 4] = h;     *(uint2*)&sBlo[nb][bK][bN + 4] = l;
            __syncthreads();
            buf = nb;
        }
    }

    // ---- epilogue: fragment -> C
#pragma unroll
    for (int mf = 0; mf < 4; mf++) {
#pragma unroll
        for (int nf = 0; nf < 4; nf++) {
            int row0 = warp_m + mf * 16 + (lane >> 2);
            int col = warp_n + nf * 8 + (lane & 3) * 2;
#pragma unroll
            for (int half = 0; half < 2; half++) {
                int row = row0 + half * 8;
                float2 val = make_float2(acc[mf][nf][half * 2],
                                         acc[mf][nf][half * 2 + 1]);
                float2* p = (float2*)(C + (long long)row * N + col);
                if (MODE == 1) {
                    float2 old = *p;
                    val.x += old.x; val.y += old.y;
                } else if (MODE == 2) {
                    const float2 b = *(const float2*)(bias + cCol * BN + col);
                    val.x += b.x; val.y += b.y;
                }
                *p = val;
            }
        }
    }
}

// ---------------------------------------------------------------------------
// Host driver (graph-capturable: kernel launches only)
// ---------------------------------------------------------------------------
static inline float* sym(const void* s) {
    void* p = nullptr;
    cudaGetSymbolAddress(&p, s);
    return (float*)p;
}

extern "C" void kernel_launch(void* const* d_in, const int* in_sizes, int n_in,
                              void* d_out, int out_size) {
    const int*   x     = (const int*)  d_in[0];
    const float* embed = (const float*)d_in[1];
    const float* Wq    = (const float*)d_in[2];
    const float* Wk    = (const float*)d_in[3];
    const float* Wv    = (const float*)d_in[4];
    const float* Wo    = (const float*)d_in[5];
    const float* Wg    = (const float*)d_in[6];
    const float* Wu    = (const float*)d_in[7];
    const float* Wd    = (const float*)d_in[8];
    const float* ln1   = (const float*)d_in[9];
    const float* ln2   = (const float*)d_in[10];
    const float* lnf   = (const float*)d_in[11];
    const float* Wout  = (const float*)d_in[12];
    const float* bout  = (const float*)d_in[13];
    float* out = (float*)d_out;

    float* h   = sym(g_h);
    float* a   = sym(g_a);
    float* q   = sym(g_q);
    float* k   = sym(g_k);
    float* v   = sym(g_v);
    float* att = sym(g_att);
    float* gg  = sym(g_g1);
    float* uu  = sym(g_g2);

    dim3 gHH(H_ / 128, S_ / 128);
    dim3 gHF(F_ / 128, S_ / 128);
    dim3 gFH(H_ / 128, S_ / 128);
    dim3 gOut(OUT_ / 128, S_ / 128);

    embed_kernel<<<(S_ * H_) / 256, 256>>>(x, embed, h);

    for (int l = 0; l < 2; l++) {
        const float* wq = Wq + (long long)l * H_ * H_;
        const float* wk = Wk + (long long)l * H_ * H_;
        const float* wv = Wv + (long long)l * H_ * H_;
        const float* wo = Wo + (long long)l * H_ * H_;
        const float* wg = Wg + (long long)l * H_ * F_;
        const float* wu = Wu + (long long)l * H_ * F_;
        const float* wd = Wd + (long long)l * F_ * H_;

        rmsnorm_kernel<<<S_, 256>>>(h, ln1 + l * H_, a);
        bgemm_kernel<0><<<gHH, 256>>>(a, wq, q, nullptr, S_, H_, H_);
        bgemm_kernel<0><<<gHH, 256>>>(a, wk, k, nullptr, S_, H_, H_);
        bgemm_kernel<0><<<gHH, 256>>>(a, wv, v, nullptr, S_, H_, H_);
        rope_kernel<<<(S_ * NH_ * 64) / 256, 256>>>(q, k);
        attn_kernel<<<dim3(NH_, S_ / 32), 256>>>(q, k, v, att);
        bgemm_kernel<1><<<gHH, 256>>>(att, wo, h, nullptr, S_, H_, H_);

        rmsnorm_kernel<<<S_, 256>>>(h, ln2 + l * H_, a);
        bgemm_kernel<0><<<gHF, 256>>>(a, wg, gg, nullptr, S_, F_, H_);
        bgemm_kernel<0><<<gHF, 256>>>(a, wu, uu, nullptr, S_, F_, H_);
        swiglu_kernel<<<(S_ * F_) / 256, 256>>>(gg, uu, S_ * F_);
        bgemm_kernel<1><<<gFH, 256>>>(gg, wd, h, nullptr, S_, H_, F_);
    }

    rmsnorm_kernel<<<S_, 256>>>(h, lnf, a);
    bgemm_kernel<2><<<gOut, 256>>>(a, Wout, out, bout, S_, OUT_, H_);
}